// round 17
// baseline (speedup 1.0000x reference)
#include <cuda_runtime.h>

#define NN 10000
#define EE 50000
#define NC 25
#define EPG 11032
#define NPG 12240

typedef unsigned long long u64;
typedef unsigned uns;

__constant__ int c_lof[NC] = {0,1,1,1,2,2,2,2,2,3,3,3,3,3,3,3,4,4,4,4,4,4,4,4,4};

__device__ float    g_h[(size_t)NN*1600];
__device__ float    g_r[(size_t)EE*640];
__device__ float    g_msg[(size_t)EE*1600];
__device__ float    g_alpha[EE*8];
__device__ int      g_cnt[NN];
__device__ int      g_rp[NN+1];
__device__ int      g_cur[NN];
__device__ int      g_ce[EE];

__device__ __forceinline__ float silu(float x){ return x/(1.f+__expf(-x)); }
__device__ __forceinline__ float4 silu4(float4 v){
  return make_float4(silu(v.x),silu(v.y),silu(v.z),silu(v.w));
}
__device__ __forceinline__ u64 bc2(float s){
  unsigned i=__float_as_uint(s); u64 r;
  asm("mov.b64 %0,{%1,%1};" : "=l"(r) : "r"(i)); return r;
}
__device__ __forceinline__ void f2(u64&a, u64 v, u64 s){
  asm("fma.rn.f32x2 %0,%1,%2,%0;" : "+l"(a) : "l"(v), "l"(s));
}
union F4U { float4 f; ulonglong2 u; };
__device__ __forceinline__ float4 tof4(ulonglong2 a){ F4U u; u.u=a; return u.f; }
__device__ __forceinline__ ulonglong2 tou2(float4 f){ F4U u; u.f=f; return u.u; }
__device__ __forceinline__ uns cvt_tf32(float f){
  uns u; asm("cvt.rna.tf32.f32 %0,%1;" : "=r"(u) : "f"(f)); return u;
}
__device__ __forceinline__ float uf(uns u){ return __uint_as_float(u); }
__device__ __forceinline__ void mma_tf32(float&c0,float&c1,float&c2,float&c3,
                                         uns a0,uns a1,uns a2,uns a3,
                                         uns b0,uns b1){
  asm("mma.sync.aligned.m16n8k8.row.col.f32.tf32.tf32.f32 "
      "{%0,%1,%2,%3},{%4,%5,%6,%7},{%8,%9},{%0,%1,%2,%3};"
      : "+f"(c0),"+f"(c1),"+f"(c2),"+f"(c3)
      : "r"(a0),"r"(a1),"r"(a2),"r"(a3),"r"(b0),"r"(b1));
}
#define FMAP(a,v,s) { f2((a).x,(v).x,(s)); f2((a).y,(v).y,(s)); }
#define FMA4(a,s,v) { (a).x=fmaf((s),(v).x,(a).x); (a).y=fmaf((s),(v).y,(a).y); \
                      (a).z=fmaf((s),(v).z,(a).z); (a).w=fmaf((s),(v).w,(a).w); }
#define MUL4(a,v)   { (a).x*=(v).x; (a).y*=(v).y; (a).z*=(v).z; (a).w*=(v).w; }
#define Z4 make_float4(0.f,0.f,0.f,0.f)
#define GBAR() asm volatile("bar.sync %0, %1;" :: "r"(grp+1), "r"(256) : "memory")

// ---------------- rmsnorm1 ----------------
__global__ void k_rms1(const float* __restrict__ x, const float* __restrict__ gamma){
  int n = blockIdx.x*4 + threadIdx.y;
  if(n >= NN) return;
  int c = threadIdx.x;
  const float* xp = x + (size_t)n*1600 + c;
  float s = 0.f;
  #pragma unroll
  for(int i=0;i<NC;i++){ float v = xp[i*64]; s += v*v; }
  float gm = rsqrtf(s*(1.f/25.f) + 1e-6f) * gamma[c];
  float* hp = g_h + (size_t)n*1600 + c;
  #pragma unroll
  for(int i=0;i<NC;i++) hp[i*64] = xp[i*64]*gm;
}

// ---------------- CSR build ----------------
__global__ void k_count(const int* __restrict__ ei){
  int e = blockIdx.x*256 + threadIdx.x;
  if(e < EE) atomicAdd(&g_cnt[ei[EE+e]], 1);
}
__global__ void k_scan(){
  __shared__ int ps[1024];
  int t = threadIdx.x;
  int v[10]; int s = 0;
  #pragma unroll
  for(int m=0;m<10;m++){ int i=t*10+m; int c=(i<NN)? g_cnt[i]:0; v[m]=s; s+=c; }
  ps[t]=s; __syncthreads();
  for(int off=1; off<1024; off<<=1){
    int val=(t>=off)? ps[t-off]:0; __syncthreads();
    ps[t]+=val; __syncthreads();
  }
  int excl=(t>0)? ps[t-1]:0;
  #pragma unroll
  for(int m=0;m<10;m++){
    int i=t*10+m;
    if(i<NN){ int o=excl+v[m]; g_rp[i]=o; g_cur[i]=o; }
  }
  if(t==0) g_rp[NN]=EE;
}
__global__ void k_fill(const int* __restrict__ ei){
  int e = blockIdx.x*256 + threadIdx.x;
  if(e < EE) g_ce[atomicAdd(&g_cur[ei[EE+e]],1)] = e;
}

// ---------------- radial MLP ----------------
__global__ __launch_bounds__(256,1)
void k_rad(const float* __restrict__ ed, const int* __restrict__ ei,
           const int* __restrict__ zn,
           const float* __restrict__ st, const float* __restrict__ tt,
           const float* __restrict__ w1, const float* __restrict__ b1,
           const float* __restrict__ w2, const float* __restrict__ b2,
           const float* __restrict__ w3, const float* __restrict__ b3)
{
  extern __shared__ float sm[];
  float* sw1=sm; float* sw2=sw1+6144; float* sw3=sw2+4096;
  float* sb1=sw3+40960; float* sb2=sb1+64; float* sb3=sb2+64;
  float* ef=sb3+640; float* h1=ef+384; float* h2=h1+256;
  int tid=threadIdx.x;
  for(int i=tid;i<6144;i+=256)  sw1[i]=w1[i];
  for(int i=tid;i<4096;i+=256)  sw2[i]=w2[i];
  for(int i=tid;i<40960;i+=256) sw3[i]=w3[i];
  if(tid<64){ sb1[tid]=b1[tid]; sb2[tid]=b2[tid]; }
  for(int i=tid;i<640;i+=256)   sb3[i]=b3[i];
  __syncthreads();

  int grp=tid>>6, t=tid&63;
  int q=grp;
  int nm=(q<2)?3:2;
  int m0=q, m1=q+4, m2=q+8;

  int iters=(EE+(int)gridDim.x*4-1)/((int)gridDim.x*4);
  for(int it=0; it<iters; it++){
    int e0=(it*(int)gridDim.x+(int)blockIdx.x)*4;
    int e=e0+grp;
    bool valid=(e<EE);
    if(t<32){
      if(valid){
        int src=ei[e], dst=ei[EE+e];
        ef[grp*96+t]   =ed[(size_t)e*32+t];
        ef[grp*96+32+t]=st[zn[src]*32+t];
        ef[grp*96+64+t]=tt[zn[dst]*32+t];
      } else {
        ef[grp*96+t]=0.f; ef[grp*96+32+t]=0.f; ef[grp*96+64+t]=0.f;
      }
    }
    __syncthreads();
    {
      float acc=sb1[t];
      const float4* ef4=(const float4*)(ef+grp*96);
      #pragma unroll
      for(int k4=0;k4<24;k4++){
        float4 v=ef4[k4];
        acc=fmaf(v.x,sw1[(k4*4+0)*64+t],acc);
        acc=fmaf(v.y,sw1[(k4*4+1)*64+t],acc);
        acc=fmaf(v.z,sw1[(k4*4+2)*64+t],acc);
        acc=fmaf(v.w,sw1[(k4*4+3)*64+t],acc);
      }
      h1[grp*64+t]=silu(acc);
    }
    __syncthreads();
    {
      float acc=sb2[t];
      const float4* h14=(const float4*)(h1+grp*64);
      #pragma unroll
      for(int k4=0;k4<16;k4++){
        float4 v=h14[k4];
        acc=fmaf(v.x,sw2[(k4*4+0)*64+t],acc);
        acc=fmaf(v.y,sw2[(k4*4+1)*64+t],acc);
        acc=fmaf(v.z,sw2[(k4*4+2)*64+t],acc);
        acc=fmaf(v.w,sw2[(k4*4+3)*64+t],acc);
      }
      h2[grp*64+t]=silu(acc);
    }
    __syncthreads();
    {
      float a0[4], a1[4], a2[4];
      #pragma unroll
      for(int ee=0;ee<4;ee++){ a0[ee]=sb3[t+64*m0]; a1[ee]=sb3[t+64*m1]; a2[ee]=(nm==3)?sb3[t+64*m2]:0.f; }
      for(int k=0;k<64;k++){
        float hh0=h2[k], hh1=h2[64+k], hh2v=h2[128+k], hh3=h2[192+k];
        float wA=sw3[k*640+t+64*m0];
        float wB=sw3[k*640+t+64*m1];
        a0[0]=fmaf(wA,hh0,a0[0]); a0[1]=fmaf(wA,hh1,a0[1]); a0[2]=fmaf(wA,hh2v,a0[2]); a0[3]=fmaf(wA,hh3,a0[3]);
        a1[0]=fmaf(wB,hh0,a1[0]); a1[1]=fmaf(wB,hh1,a1[1]); a1[2]=fmaf(wB,hh2v,a1[2]); a1[3]=fmaf(wB,hh3,a1[3]);
        if(nm==3){
          float wC=sw3[k*640+t+64*m2];
          a2[0]=fmaf(wC,hh0,a2[0]); a2[1]=fmaf(wC,hh1,a2[1]); a2[2]=fmaf(wC,hh2v,a2[2]); a2[3]=fmaf(wC,hh3,a2[3]);
        }
      }
      #pragma unroll
      for(int ee=0;ee<4;ee++){
        int eo=e0+ee;
        if(eo<EE){
          g_r[(size_t)eo*640+t+64*m0]=a0[ee];
          g_r[(size_t)eo*640+t+64*m1]=a1[ee];
          if(nm==3) g_r[(size_t)eo*640+t+64*m2]=a2[ee];
        }
      }
    }
    __syncthreads();
  }
}

// ---------------- per-edge kernel: all-mma, tf32-bits-resident smem ----------------
__global__ __launch_bounds__(512,1)
void k_edge(const float* __restrict__ wigner, const int* __restrict__ ei,
            const float* __restrict__ W1, const float* __restrict__ W0,
            const float* __restrict__ adot, const float* __restrict__ tg,
            const float* __restrict__ fg)
{
  extern __shared__ float sm[];
  uns*   sW1p = (uns*)sm;   // 9216 (128x72)
  float* sW0  = sm+9216;    // 24576
  uns*   sTG  = (uns*)(sm+33792); // 900
  uns*   sFG  = sTG+900;    // 900
  float* sAD  = (float*)(sFG+900); // 128
  float* pe   = sAD+128;    // 2*EPG
  int tid=threadIdx.x;
  for(int i=tid;i<8192;i+=512){ int c=i>>6,h=i&63; sW1p[c*72+h]=cvt_tf32(W1[i]); }
  for(int i=tid;i<24576;i+=512){ int o=i>>7,c=i&127; sW0[i]=W0[c*192+o]; }
  for(int i=tid;i<900;i+=512){ sTG[i]=cvt_tf32(tg[i]); sFG[i]=cvt_tf32(fg[i]); }
  if(tid<128) sAD[tid]=adot[tid];
  __syncthreads();

  int grp = tid>>8, t = tid&255;
  float* base  = pe + grp*EPG;
  uns* swigA = (uns*)base;        // 900 (25x36)
  uns* swigB = swigA+900;         // 900
  uns* scat  = swigB+900;         // 3300 (25x132)
  float* srr = (float*)(scat+3300); // 640
  uns* sxe   = (uns*)(srr+640);   // 3300 (25x132); aliased sgrid (40x72)
  float* sextra=(float*)(sxe+3300); // 192
  uns* smsg  = (uns*)(sextra+192);// 1800 (25x72)
  uns* sgrid = sxe;
  uns* smact = smsg;

  int w=t>>5, lane=t&31;
  int mt=w&1, ng=w>>1;
  int fr=lane>>2, cq=lane&3;
  int rowA=mt*16+fr, rowB=rowA+8;

  int stride = (int)gridDim.x*2;
  int e = (int)blockIdx.x*2 + grp;
  int p = 0;

  {
    const float* wp=wigner+(size_t)e*625;
    for(int i=t;i<625;i+=256) swigA[(i/25)*36+(i%25)]=cvt_tf32(wp[i]);
    int src=ei[e], dst=ei[EE+e];
    const float4* hs=(const float4*)(g_h+(size_t)src*1600);
    const float4* hd=(const float4*)(g_h+(size_t)dst*1600);
    uint4* cat4=(uint4*)scat;
    for(int i=t;i<800;i+=256){
      int j=i>>5,qq=i&31;
      float4 v=(qq<16)?hs[j*16+qq]:hd[j*16+qq-16];
      cat4[j*33+qq]=make_uint4(cvt_tf32(v.x),cvt_tf32(v.y),cvt_tf32(v.z),cvt_tf32(v.w));
    }
    const float4* rp4=(const float4*)(g_r+(size_t)e*640);
    float4* srr4=(float4*)srr;
    for(int i=t;i<160;i+=256) srr4[i]=rp4[i];
  }

  for(; e<EE; e+=stride){
    int en = e + stride; if(en >= EE) en = e;
    uns* swig  = p? swigB : swigA;
    uns* swigN = p? swigA : swigB;
    GBAR();

    // xe = (wig @ cat)*r[EXPAND]
    {
      float acc[4][4]={};
      #pragma unroll
      for(int kc=0;kc<3;kc++){
        int k0=kc*8;
        uns a0=swig[rowA*36+k0+cq];
        uns a1=swig[rowB*36+k0+cq];
        uns a2=swig[rowA*36+k0+cq+4];
        uns a3=swig[rowB*36+k0+cq+4];
        #pragma unroll
        for(int nt=0;nt<4;nt++){
          int nb=ng*32+nt*8;
          uns b0=scat[(k0+cq)*132+nb+fr];
          uns b1=scat[(k0+cq+4)*132+nb+fr];
          mma_tf32(acc[nt][0],acc[nt][1],acc[nt][2],acc[nt][3],a0,a1,a2,a3,b0,b1);
        }
      }
      float wa0=uf(swig[rowA*36+24]), wa1=uf(swig[rowB*36+24]);
      int lof0=c_lof[rowA<25?rowA:0], lof1=c_lof[rowB<25?rowB:0];
      #pragma unroll
      for(int nt=0;nt<4;nt++){
        int col=ng*32+nt*8+2*cq;
        float bt0=uf(scat[24*132+col]), bt1=uf(scat[24*132+col+1]);
        acc[nt][0]=fmaf(wa0,bt0,acc[nt][0]); acc[nt][1]=fmaf(wa0,bt1,acc[nt][1]);
        acc[nt][2]=fmaf(wa1,bt0,acc[nt][2]); acc[nt][3]=fmaf(wa1,bt1,acc[nt][3]);
        if(rowA<25){
          sxe[rowA*132+col]  =cvt_tf32(acc[nt][0]*srr[lof0*128+col]);
          sxe[rowA*132+col+1]=cvt_tf32(acc[nt][1]*srr[lof0*128+col+1]);
        }
        if(rowB<25){
          sxe[rowB*132+col]  =cvt_tf32(acc[nt][2]*srr[lof1*128+col]);
          sxe[rowB*132+col+1]=cvt_tf32(acc[nt][3]*srr[lof1*128+col+1]);
        }
      }
    }
    GBAR();

    // prefetch next edge (cvt to tf32 bits inline)
    {
      const float* wp=wigner+(size_t)en*625;
      for(int i=t;i<625;i+=256) swigN[(i/25)*36+(i%25)]=cvt_tf32(wp[i]);
      int nsrc=ei[en], ndst=ei[EE+en];
      const float4* hs=(const float4*)(g_h+(size_t)nsrc*1600);
      const float4* hd=(const float4*)(g_h+(size_t)ndst*1600);
      uint4* cat4=(uint4*)scat;
      for(int i=t;i<800;i+=256){
        int j=i>>5,qq=i&31;
        float4 v=(qq<16)?hs[j*16+qq]:hd[j*16+qq-16];
        cat4[j*33+qq]=make_uint4(cvt_tf32(v.x),cvt_tf32(v.y),cvt_tf32(v.z),cvt_tf32(v.w));
      }
      const float4* rp4=(const float4*)(g_r+(size_t)en*640);
      float4* srr4=(float4*)srr;
      for(int i=t;i<160;i+=256) srr4[i]=rp4[i];
    }

    // msg = xe @ W1 (mma K=128), extra by t<192
    {
      const uns* A0=sxe+rowA*132;
      const uns* A1=sxe+rowB*132;
      float acc[2][4]={};
      #pragma unroll
      for(int kc=0;kc<16;kc++){
        int k0=kc*8;
        uns a0=A0[k0+cq];
        uns a1=A1[k0+cq];
        uns a2=A0[k0+cq+4];
        uns a3=A1[k0+cq+4];
        #pragma unroll
        for(int nt=0;nt<2;nt++){
          int nb=ng*16+nt*8;
          uns b0=sW1p[(k0+cq)*72+nb+fr];
          uns b1=sW1p[(k0+cq+4)*72+nb+fr];
          mma_tf32(acc[nt][0],acc[nt][1],acc[nt][2],acc[nt][3],a0,a1,a2,a3,b0,b1);
        }
      }
      #pragma unroll
      for(int nt=0;nt<2;nt++){
        int col=ng*16+nt*8+2*cq;
        if(rowA<25){ smsg[rowA*72+col]=cvt_tf32(acc[nt][0]); smsg[rowA*72+col+1]=cvt_tf32(acc[nt][1]); }
        if(rowB<25){ smsg[rowB*72+col]=cvt_tf32(acc[nt][2]); smsg[rowB*72+col+1]=cvt_tf32(acc[nt][3]); }
      }
    }
    if(t<192){
      const uint4* x0=(const uint4*)sxe;
      const float4* wv4=(const float4*)(sW0+t*128);
      float4 acc=Z4;
      #pragma unroll 8
      for(int k=0;k<32;k++){ uint4 xv=x0[k]; float4 wv=wv4[k];
        acc.x=fmaf(uf(xv.x),wv.x,acc.x); acc.y=fmaf(uf(xv.y),wv.y,acc.y);
        acc.z=fmaf(uf(xv.z),wv.z,acc.z); acc.w=fmaf(uf(xv.w),wv.w,acc.w); }
      sextra[t]=acc.x+acc.y+acc.z+acc.w;
    }
    GBAR();

    // grid = silu(to_grid @ msg) via mma, + alpha by t<8
    if(t<8){
      float acc=0.f;
      #pragma unroll
      for(int a=0;a<16;a++){ float v=sextra[t*16+a]; acc=fmaf(silu(v),sAD[t*16+a],acc); }
      g_alpha[e*8+t]=acc;
    }
    {
      #pragma unroll
      for(int tk=0;tk<2;tk++){
        int task = w + tk*8;
        if(task<12){
          int gmt=task>>2, gnq=task&3;
          int rowG=gmt*16+fr, rowG2=rowG+8;
          float acc[2][4]={};
          #pragma unroll
          for(int kc=0;kc<3;kc++){
            int k0=kc*8;
            uns a0=sTG[rowG*25+k0+cq];
            uns a1=sTG[rowG2*25+k0+cq];
            uns a2=sTG[rowG*25+k0+cq+4];
            uns a3=sTG[rowG2*25+k0+cq+4];
            #pragma unroll
            for(int nt=0;nt<2;nt++){
              int nb=gnq*16+nt*8;
              uns b0=smsg[(k0+cq)*72+nb+fr];
              uns b1=smsg[(k0+cq+4)*72+nb+fr];
              mma_tf32(acc[nt][0],acc[nt][1],acc[nt][2],acc[nt][3],a0,a1,a2,a3,b0,b1);
            }
          }
          float wa0=uf(sTG[rowG*25+24]), wa1=uf(sTG[rowG2*25+24]);
          #pragma unroll
          for(int nt=0;nt<2;nt++){
            int col=gnq*16+nt*8+2*cq;
            float bt0=uf(smsg[24*72+col]), bt1=uf(smsg[24*72+col+1]);
            acc[nt][0]=fmaf(wa0,bt0,acc[nt][0]); acc[nt][1]=fmaf(wa0,bt1,acc[nt][1]);
            acc[nt][2]=fmaf(wa1,bt0,acc[nt][2]); acc[nt][3]=fmaf(wa1,bt1,acc[nt][3]);
            if(rowG<36){ sgrid[rowG*72+col]=cvt_tf32(silu(acc[nt][0])); sgrid[rowG*72+col+1]=cvt_tf32(silu(acc[nt][1])); }
            if(rowG2<36){ sgrid[rowG2*72+col]=cvt_tf32(silu(acc[nt][2])); sgrid[rowG2*72+col+1]=cvt_tf32(silu(acc[nt][3])); }
          }
        }
      }
      { int row=36+(t>>6), col=t&63; sgrid[row*72+col]=0u; }
    }
    GBAR();

    // mact = [silu(gate); from_grid @ grid] via mma K=40
    {
      float acc[2][4]={};
      #pragma unroll
      for(int kc=0;kc<5;kc++){
        int k0=kc*8;
        uns a0=sFG[rowA*36+k0+cq];
        uns a1=sFG[rowB*36+k0+cq];
        uns a2=sFG[rowA*36+k0+cq+4];
        uns a3=sFG[rowB*36+k0+cq+4];
        #pragma unroll
        for(int nt=0;nt<2;nt++){
          int nb=ng*16+nt*8;
          uns b0=sgrid[(k0+cq)*72+nb+fr];
          uns b1=sgrid[(k0+cq+4)*72+nb+fr];
          mma_tf32(acc[nt][0],acc[nt][1],acc[nt][2],acc[nt][3],a0,a1,a2,a3,b0,b1);
        }
      }
      #pragma unroll
      for(int nt=0;nt<2;nt++){
        int col=ng*16+nt*8+2*cq;
        if(rowA<25){
          float v0=acc[nt][0], v1=acc[nt][1];
          if(rowA==0){ v0=silu(sextra[128+col]); v1=silu(sextra[128+col+1]); }
          smact[rowA*72+col]=cvt_tf32(v0); smact[rowA*72+col+1]=cvt_tf32(v1);
        }
        if(rowB<25){ smact[rowB*72+col]=cvt_tf32(acc[nt][2]); smact[rowB*72+col+1]=cvt_tf32(acc[nt][3]); }
      }
    }
    GBAR();

    // rotated = wig^T @ mact
    {
      float acc[2][4]={};
      #pragma unroll
      for(int kc=0;kc<3;kc++){
        int k0=kc*8;
        uns a0=swig[(k0+cq)*36+rowA];
        uns a1=swig[(k0+cq)*36+rowB];
        uns a2=swig[(k0+cq+4)*36+rowA];
        uns a3=swig[(k0+cq+4)*36+rowB];
        #pragma unroll
        for(int nt=0;nt<2;nt++){
          int nb=ng*16+nt*8;
          uns b0=smact[(k0+cq)*72+nb+fr];
          uns b1=smact[(k0+cq+4)*72+nb+fr];
          mma_tf32(acc[nt][0],acc[nt][1],acc[nt][2],acc[nt][3],a0,a1,a2,a3,b0,b1);
        }
      }
      float wa0=uf(swig[24*36+rowA]), wa1=uf(swig[24*36+rowB]);
      float* op=g_msg+(size_t)e*1600;
      #pragma unroll
      for(int nt=0;nt<2;nt++){
        int col=ng*16+nt*8+2*cq;
        float bt0=uf(smact[24*72+col]), bt1=uf(smact[24*72+col+1]);
        acc[nt][0]=fmaf(wa0,bt0,acc[nt][0]); acc[nt][1]=fmaf(wa0,bt1,acc[nt][1]);
        acc[nt][2]=fmaf(wa1,bt0,acc[nt][2]); acc[nt][3]=fmaf(wa1,bt1,acc[nt][3]);
        if(rowA<25) *(float2*)(op+rowA*64+col)=make_float2(acc[nt][0],acc[nt][1]);
        if(rowB<25) *(float2*)(op+rowB*64+col)=make_float2(acc[nt][2],acc[nt][3]);
      }
    }
    p ^= 1;
  }
}

// ---------------- node: all-mma FFN, tf32-bits-resident ----------------
__global__ __launch_bounds__(512,1)
void k_node(const float* __restrict__ x, float* __restrict__ out,
            const float* __restrict__ po, const float* __restrict__ g2w,
            const float* __restrict__ glw, const float* __restrict__ glb,
            const float* __restrict__ fw1, const float* __restrict__ fb1,
            const float* __restrict__ fw2, const float* __restrict__ fb2,
            const float* __restrict__ tg, const float* __restrict__ fg)
{
  extern __shared__ float sm[];
  float* sPO  = sm;                     // 4096
  float* sGL  = sPO+4096;               // 8192
  uns* sW1fp=(uns*)(sGL+8192);          // 8704
  uns* sW2p =(uns*)(sGL+16896);         // 9216
  uns* sTG  = (uns*)(sm+30208);         // 900
  uns* sFG  = sTG+900;                  // 900
  float* sGLB = (float*)(sFG+900);      // 128
  float* sB1  = sGLB+128;               // 128
  float* sB2  = sB1+128;                // 64
  float* sGam = sB2+64;                 // 64
  float* pn   = sGam+64;                // 2*NPG
  int tid=threadIdx.x;
  for(int i=tid;i<4096;i+=512) sPO[i]=po[i];
  for(int i=tid;i<8192;i+=512) sGL[i]=glw[i];
  for(int i=tid;i<8192;i+=512){ int c=i>>7,f=i&127; sW1fp[c*136+f]=cvt_tf32(fw1[i]); }
  for(int i=tid;i<8192;i+=512){ int f=i>>6,c=i&63; sW2p[f*72+c]=cvt_tf32(fw2[i]); }
  for(int i=tid;i<900;i+=512){ sTG[i]=cvt_tf32(tg[i]); sFG[i]=cvt_tf32(fg[i]); }
  if(tid<128){ sGLB[tid]=glb[tid]; sB1[tid]=fb1[tid]; }
  if(tid<64){ sB2[tid]=fb2[tid]; sGam[tid]=g2w[tid]; }
  __syncthreads();

  int grp=tid>>8, t=tid&255;
  float* base = pn + grp*NPG;
  float* sCE  = base;          // 64
  float* sXN  = base+64;       // 1600
  uns*   sH   = (uns*)(base+1664);  // 1700 (25x68)
  float* sGate= base+3364;     // 128
  uns*   sF1  = (uns*)(base+3492);  // 3300 (25x132); sAL/sEW alias
  uns*   sG2  = (uns*)(base+6792);  // 5440 (40x136); sA alias
  float* sA   = (float*)sG2;
  float* sAL  = (float*)sF1;   // 512
  float* sEW  = sAL+512;       // 512
  int* sCEi = (int*)sCE;

  int c4=t&15, rg=t>>4;
  int w=t>>5, lane=t&31;
  int mt=w&1, ng=w>>1;
  int fr=lane>>2, cq=lane&3;
  int rowA=mt*16+fr, rowB=rowA+8;

  for(int nb=blockIdx.x*2; nb<NN; nb+=gridDim.x*2){
    int n = nb + grp;
    int beg=g_rp[n], end=g_rp[n+1];
    int deg=end-beg;
    float4* sA4=(float4*)sA;
    for(int i=t;i<400;i+=256) sA4[i]=Z4;
    if(t<16) sGate[t] = (t<8)? -3.0e38f : 0.f;
    GBAR();

    for(int k0=beg; k0<end; k0+=64){
      int kc=min(64,end-k0);
      for(int idx=t; idx<kc; idx+=256) sCEi[idx]=g_ce[k0+idx];
      GBAR();
      for(int idx=t; idx<kc*2; idx+=256){
        int j=idx>>1, q=idx&1;
        ((float4*)sAL)[j*2+q] = ((const float4*)(g_alpha+(size_t)sCEi[j]*8))[q];
      }
      GBAR();
      if(t<8){
        float m=sGate[t], s=sGate[8+t];
        for(int j=0;j<kc;j++){
          float a=sAL[j*8+t];
          if(a>m){ s=s*__expf(m-a)+1.f; m=a; }
          else    s+=__expf(a-m);
        }
        sGate[t]=m; sGate[8+t]=s;
      }
      GBAR();
    }
    if(t<8) sGate[8+t]=1.f/(sGate[8+t]+1e-8f);
    GBAR();

    for(int k0=beg; k0<end; k0+=64){
      int kc=min(64,end-k0);
      if(deg>64){
        for(int idx=t; idx<kc; idx+=256) sCEi[idx]=g_ce[k0+idx];
        GBAR();
        for(int idx=t; idx<kc*2; idx+=256){
          int j=idx>>1, q=idx&1;
          ((float4*)sAL)[j*2+q] = ((const float4*)(g_alpha+(size_t)sCEi[j]*8))[q];
        }
      }
      GBAR();
      for(int idx=t; idx<kc*8; idx+=256)
        sEW[idx]=__expf(sAL[idx]-sGate[idx&7])*sGate[8+(idx&7)];
      GBAR();
      for(int j=0;j<kc;j++){
        int e=sCEi[j];
        const float4* mp=(const float4*)(g_msg+(size_t)e*1600);
        const float* wj = sEW + j*8;
        for(int i=t;i<400;i+=256){
          float wv=wj[(i&15)>>1];
          float4 v=mp[i];
          float4 a=sA4[i];
          FMA4(a,wv,v);
          sA4[i]=a;
        }
      }
      GBAR();
    }

    // XN = x + agg @ proj_out (FFMA2)
    {
      int r0=rg, r1=rg+16; bool v1=(r1<25);
      const float4* x4g=(const float4*)(x+(size_t)n*1600);
      const ulonglong2* p4=(const ulonglong2*)sPO;
      ulonglong2 a0=tou2(x4g[r0*16+c4]);
      ulonglong2 a1=tou2(v1? x4g[r1*16+c4] : Z4);
      #pragma unroll 8
      for(int k=0;k<64;k++){
        ulonglong2 wv=p4[k*16+c4];
        u64 s0=bc2(sA[r0*64+k]); FMAP(a0,wv,s0);
        if(v1){ u64 s1=bc2(sA[r1*64+k]); FMAP(a1,wv,s1); }
      }
      ((ulonglong2*)sXN)[r0*16+c4]=a0;
      if(v1) ((ulonglong2*)sXN)[r1*16+c4]=a1;
    }
    GBAR();
    if(t<64){
      float s=0.f;
      #pragma unroll
      for(int i=0;i<NC;i++){ float v=sXN[i*64+t]; s=fmaf(v,v,s); }
      sGate[t]=rsqrtf(s*(1.f/25.f)+1e-6f)*sGam[t];
    }
    GBAR();
    {
      uint4* sH4=(uint4*)sH;
      const float4* xn4=(const float4*)sXN;
      const float4* rv4=(const float4*)sGate;
      for(int i=t;i<400;i+=256){
        int row=i>>4, q=i&15;
        float4 v=xn4[i], r=rv4[q]; MUL4(v,r);
        sH4[row*17+q]=make_uint4(cvt_tf32(v.x),cvt_tf32(v.y),cvt_tf32(v.z),cvt_tf32(v.w));
      }
    }
    GBAR();
    float gacc=0.f;
    if(t<128){
      gacc=sGLB[t];
      #pragma unroll 8
      for(int c=0;c<64;c++) gacc=fmaf(uf(sH[c]),sGL[c*128+t],gacc);
    }
    GBAR();
    if(t<128) sGate[t]=gacc;
    // F1 = h @ ffn_w1 (+b1 row0) via mma K=64
    {
      float acc[4][4]={};
      #pragma unroll
      for(int kc=0;kc<8;kc++){
        int k0=kc*8;
        uns a0=sH[rowA*68+k0+cq];
        uns a1=sH[rowB*68+k0+cq];
        uns a2=sH[rowA*68+k0+cq+4];
        uns a3=sH[rowB*68+k0+cq+4];
        #pragma unroll
        for(int nt=0;nt<4;nt++){
          int nbb=ng*32+nt*8;
          uns b0=sW1fp[(k0+cq)*136+nbb+fr];
          uns b1=sW1fp[(k0+cq+4)*136+nbb+fr];
          mma_tf32(acc[nt][0],acc[nt][1],acc[nt][2],acc[nt][3],a0,a1,a2,a3,b0,b1);
        }
      }
      #pragma unroll
      for(int nt=0;nt<4;nt++){
        int col=ng*32+nt*8+2*cq;
        if(rowA<25){
          float v0=acc[nt][0], v1=acc[nt][1];
          if(rowA==0){ v0+=sB1[col]; v1+=sB1[col+1]; }
          sF1[rowA*132+col]=cvt_tf32(v0); sF1[rowA*132+col+1]=cvt_tf32(v1);
        }
        if(rowB<25){ sF1[rowB*132+col]=cvt_tf32(acc[nt][2]); sF1[rowB*132+col+1]=cvt_tf32(acc[nt][3]); }
      }
    }
    GBAR();
    // G2 = silu(to_grid @ F1) via mma: 24 tasks
    {
      #pragma unroll
      for(int tk=0;tk<3;tk++){
        int task = w + tk*8;
        int gmt=task>>3, gnq=task&7;
        int rowG=gmt*16+fr, rowG2=rowG+8;
        float acc[2][4]={};
        #pragma unroll
        for(int kc=0;kc<3;kc++){
          int k0=kc*8;
          uns a0=sTG[rowG*25+k0+cq];
          uns a1=sTG[rowG2*25+k0+cq];
          uns a2=sTG[rowG*25+k0+cq+4];
          uns a3=sTG[rowG2*25+k0+cq+4];
          #pragma unroll
          for(int nt=0;nt<2;nt++){
            int nbb=gnq*16+nt*8;
            uns b0=sF1[(k0+cq)*132+nbb+fr];
            uns b1=sF1[(k0+cq+4)*132+nbb+fr];
            mma_tf32(acc[nt][0],acc[nt][1],acc[nt][2],acc[nt][3],a0,a1,a2,a3,b0,b1);
          }
        }
        float wa0=uf(sTG[rowG*25+24]), wa1=uf(sTG[rowG2*25+24]);
        #pragma unroll
        for(int nt=0;nt<2;nt++){
          int col=gnq*16+nt*8+2*cq;
          float bt0=uf(sF1[24*132+col]), bt1=uf(sF1[24*132+col+1]);
          acc[nt][0]=fmaf(wa0,bt0,acc[nt][0]); acc[nt][1]=fmaf(wa0,bt1,acc[nt][1]);
          acc[nt][2]=fmaf(wa1,bt0,acc[nt][2]); acc[nt][3]=fmaf(wa1,bt1,acc[nt][3]);
          if(rowG<36){ sG2[rowG*136+col]=cvt_tf32(silu(acc[nt][0])); sG2[rowG*136+col+1]=cvt_tf32(silu(acc[nt][1])); }
          if(rowG2<36){ sG2[rowG2*136+col]=cvt_tf32(silu(acc[nt][2])); sG2[rowG2*136+col+1]=cvt_tf32(silu(acc[nt][3])); }
        }
      }
      { int row=36+(t>>6), col=t&63; sG2[row*136+col]=0u; sG2[row*136+col+64]=0u; }
    }
    GBAR();
    // F1 := [silu(gate); from_grid @ G2] via mma K=40
    {
      float acc[4][4]={};
      #pragma unroll
      for(int kc=0;kc<5;kc++){
        int k0=kc*8;
        uns a0=sFG[rowA*36+k0+cq];
        uns a1=sFG[rowB*36+k0+cq];
        uns a2=sFG[rowA*36+k0+cq+4];
        uns a3=sFG[rowB*36+k0+cq+4];
        #pragma unroll
        for(int nt=0;nt<4;nt++){
          int nbb=ng*32+nt*8;
          uns b0=sG2[(k0+cq)*136+nbb+fr];
          uns b1=sG2[(k0+cq+4)*136+nbb+fr];
          mma_tf32(acc[nt][0],acc[nt][1],acc[nt][2],acc[nt][3],a0,a1,a2,a3,b0,b1);
        }
      }
      #pragma unroll
      for(int nt=0;nt<4;nt++){
        int col=ng*32+nt*8+2*cq;
        if(rowA<25){
          float v0=acc[nt][0], v1=acc[nt][1];
          if(rowA==0){ v0=silu(sGate[col]); v1=silu(sGate[col+1]); }
          sF1[rowA*132+col]=cvt_tf32(v0); sF1[rowA*132+col+1]=cvt_tf32(v1);
        }
        if(rowB<25){ sF1[rowB*132+col]=cvt_tf32(acc[nt][2]); sF1[rowB*132+col+1]=cvt_tf32(acc[nt][3]); }
      }
    }
    GBAR();
    // out = XN + F1 @ ffn_w2 (+b2 row0) via mma K=128
    {
      float acc[2][4]={};
      #pragma unroll
      for(int kc=0;kc<16;kc++){
        int k0=kc*8;
        uns a0=sF1[rowA*132+k0+cq];
        uns a1=sF1[rowB*132+k0+cq];
        uns a2=sF1[rowA*132+k0+cq+4];
        uns a3=sF1[rowB*132+k0+cq+4];
        #pragma unroll
        for(int nt=0;nt<2;nt++){
          int nbb=ng*16+nt*8;
          uns b0=sW2p[(k0+cq)*72+nbb+fr];
          uns b1=sW2p[(k0+cq+4)*72+nbb+fr];
          mma_tf32(acc[nt][0],acc[nt][1],acc[nt][2],acc[nt][3],a0,a1,a2,a3,b0,b1);
        }
      }
      float* op=out+(size_t)n*1600;
      #pragma unroll
      for(int nt=0;nt<2;nt++){
        int col=ng*16+nt*8+2*cq;
        if(rowA<25){
          float v0=sXN[rowA*64+col]+acc[nt][0];
          float v1=sXN[rowA*64+col+1]+acc[nt][1];
          if(rowA==0){ v0+=sB2[col]; v1+=sB2[col+1]; }
          *(float2*)(op+rowA*64+col)=make_float2(v0,v1);
        }
        if(rowB<25){
          float v0=sXN[rowB*64+col]+acc[nt][2];
          float v1=sXN[rowB*64+col+1]+acc[nt][3];
          *(float2*)(op+rowB*64+col)=make_float2(v0,v1);
        }
      }
    }
    GBAR();
  }
}

extern "C" void kernel_launch(void* const* d_in, const int* in_sizes, int n_in,
                              void* d_out, int out_size) {
  const float* x    = (const float*)d_in[0];
  const int*   ei   = (const int*)d_in[1];
  const int*   zn   = (const int*)d_in[2];
  const float* ed   = (const float*)d_in[3];
  const float* wigr = (const float*)d_in[4];
  const float* stab = (const float*)d_in[5];
  const float* ttab = (const float*)d_in[6];
  const float* rw1  = (const float*)d_in[7];
  const float* rb1  = (const float*)d_in[8];
  const float* rw2  = (const float*)d_in[9];
  const float* rb2  = (const float*)d_in[10];
  const float* rw3  = (const float*)d_in[11];
  const float* rb3  = (const float*)d_in[12];
  const float* W1   = (const float*)d_in[13];
  const float* W0e  = (const float*)d_in[14];
  const float* adot = (const float*)d_in[15];
  const float* tg   = (const float*)d_in[16];
  const float* fg   = (const float*)d_in[17];
  const float* po   = (const float*)d_in[18];
  const float* gm1  = (const float*)d_in[19];
  const float* gm2  = (const float*)d_in[20];
  const float* glw  = (const float*)d_in[21];
  const float* glb  = (const float*)d_in[22];
  const float* fw1  = (const float*)d_in[23];
  const float* fb1  = (const float*)d_in[24];
  const float* fw2  = (const float*)d_in[25];
  const float* fb2  = (const float*)d_in[26];
  float* out = (float*)d_out;

  void *pcnt;
  cudaGetSymbolAddress(&pcnt, g_cnt);
  cudaMemsetAsync(pcnt, 0, NN*sizeof(int));

  const int RAD_SMEM  = 52864*4;
  const int EDGE_SMEM = (9216+24576+900+900+128 + 2*EPG)*4;
  const int NODE_SMEM = (32392 + 2*NPG)*4;
  cudaFuncSetAttribute(k_rad,  cudaFuncAttributeMaxDynamicSharedMemorySize, RAD_SMEM);
  cudaFuncSetAttribute(k_edge, cudaFuncAttributeMaxDynamicSharedMemorySize, EDGE_SMEM);
  cudaFuncSetAttribute(k_node, cudaFuncAttributeMaxDynamicSharedMemorySize, NODE_SMEM);

  k_rms1<<<(NN+3)/4, dim3(64,4)>>>(x, gm1);
  k_count<<<(EE+255)/256, 256>>>(ei);
  k_scan<<<1, 1024>>>();
  k_fill<<<(EE+255)/256, 256>>>(ei);
  k_rad<<<296, 256, RAD_SMEM>>>(ed, ei, zn, stab, ttab, rw1, rb1, rw2, rb2, rw3, rb3);
  k_edge<<<148, 512, EDGE_SMEM>>>(wigr, ei, W1, W0e, adot, tg, fg);
  k_node<<<148, 512, NODE_SMEM>>>(x, out, po, gm2, glw, glb, fw1, fb1, fw2, fb2, tg, fg);
}